// round 2
// baseline (speedup 1.0000x reference)
#include <cuda_runtime.h>
#include <cstdint>

#define D   512
#define TE  32
#define NT  256
#define KC  16

// scatter-sum scratch: agg[NG][D]
__device__ float g_agg[65536 * 512];

__device__ __forceinline__ unsigned long long pack2(float a) {
    unsigned long long r;
    asm("mov.b64 %0, {%1, %1};" : "=l"(r) : "r"(__float_as_uint(a)));
    return r;
}
__device__ __forceinline__ void fma2(float2& c, unsigned long long a2, float2 w) {
    unsigned long long cc = *reinterpret_cast<unsigned long long*>(&c);
    unsigned long long ww = *reinterpret_cast<unsigned long long*>(&w);
    asm("fma.rn.f32x2 %0, %1, %2, %0;" : "+l"(cc) : "l"(a2), "l"(ww));
    c = *reinterpret_cast<float2*>(&cc);
}
__device__ __forceinline__ float warp_sum(float v) {
#pragma unroll
    for (int o = 16; o; o >>= 1) v += __shfl_xor_sync(0xffffffffu, v, o);
    return v;
}
__device__ __forceinline__ float silu(float x) {
    return __fdividef(x, 1.0f + __expf(-x));
}

__device__ __forceinline__ void init_bias(float2 acc[4][8], const float* __restrict__ b, int tx) {
#pragma unroll
    for (int j = 0; j < 8; ++j) {
        float2 bb = *reinterpret_cast<const float2*>(&b[64 * j + 2 * tx]);
#pragma unroll
        for (int i = 0; i < 4; ++i) acc[i][j] = bb;
    }
}

// acc[i][j] covers row (wid*4+i), cols (64*j + 2*tx, +1)
template <class StageA, class ReadA>
__device__ __forceinline__ void gemm_acc(float2 acc[4][8], const float* __restrict__ W,
                                         int Ktot, float* sW, int tid, int wid, int tx,
                                         StageA stageA, ReadA readA) {
    for (int k0 = 0; k0 < Ktot; k0 += KC) {
        // stage W chunk [KC][D] -> shared (coalesced float4)
        const float4* Wg = reinterpret_cast<const float4*>(W + (size_t)k0 * D);
        float4* sW4 = reinterpret_cast<float4*>(sW);
#pragma unroll
        for (int m = 0; m < (KC * D / 4) / NT; ++m)
            sW4[tid + m * NT] = Wg[tid + m * NT];
        stageA(k0);
        __syncthreads();
#pragma unroll
        for (int kk = 0; kk < KC; ++kk) {
            unsigned long long a2[4];
#pragma unroll
            for (int i = 0; i < 4; ++i)
                a2[i] = pack2(readA(wid * 4 + i, k0 + kk, kk));
#pragma unroll
            for (int j = 0; j < 8; ++j) {
                float2 w = *reinterpret_cast<const float2*>(&sW[kk * D + 64 * j + 2 * tx]);
#pragma unroll
                for (int i = 0; i < 4; ++i) fma2(acc[i][j], a2[i], w);
            }
        }
        __syncthreads();
    }
}

__device__ __forceinline__ void silu_store(float2 acc[4][8], float* dst, int wid, int tx) {
#pragma unroll
    for (int i = 0; i < 4; ++i) {
        int r = wid * 4 + i;
#pragma unroll
        for (int j = 0; j < 8; ++j) {
            float2 v = acc[i][j];
            v.x = silu(v.x); v.y = silu(v.y);
            *reinterpret_cast<float2*>(&dst[r * D + 64 * j + 2 * tx]) = v;
        }
    }
}

__device__ __forceinline__ void layernorm(float2 acc[4][8], const float* __restrict__ g,
                                          const float* __restrict__ beta, int tx) {
#pragma unroll
    for (int i = 0; i < 4; ++i) {
        float s = 0.f, ss = 0.f;
#pragma unroll
        for (int j = 0; j < 8; ++j) {
            s  += acc[i][j].x + acc[i][j].y;
            ss += acc[i][j].x * acc[i][j].x + acc[i][j].y * acc[i][j].y;
        }
        s = warp_sum(s); ss = warp_sum(ss);
        float m    = s * (1.0f / D);
        float var  = ss * (1.0f / D) - m * m;
        float rstd = rsqrtf(var + 1e-5f);
#pragma unroll
        for (int j = 0; j < 8; ++j) {
            int c = 64 * j + 2 * tx;
            float2 gg = *reinterpret_cast<const float2*>(&g[c]);
            float2 bb = *reinterpret_cast<const float2*>(&beta[c]);
            acc[i][j].x = (acc[i][j].x - m) * rstd * gg.x + bb.x;
            acc[i][j].y = (acc[i][j].y - m) * rstd * gg.y + bb.y;
        }
    }
}

__global__ void zero_kernel(int n4) {
    int i = blockIdx.x * blockDim.x + threadIdx.x;
    if (i < n4) *reinterpret_cast<float4*>(&g_agg[(size_t)i * 4]) = make_float4(0.f, 0.f, 0.f, 0.f);
}

// Fused: emb MLP -> edge MLP -> residual -> atomic scatter into g_agg
__global__ void __launch_bounds__(NT, 1) edge_kernel(
    const float* __restrict__ gridf, const float* __restrict__ mesh,
    const int* __restrict__ eidx, const float* __restrict__ efeat,
    const float* __restrict__ embW0, const float* __restrict__ embb0,
    const float* __restrict__ embW1, const float* __restrict__ embb1,
    const float* __restrict__ embg,  const float* __restrict__ embbt,
    const float* __restrict__ edW0,  const float* __restrict__ edb0,
    const float* __restrict__ edW1,  const float* __restrict__ edb1,
    const float* __restrict__ edg,   const float* __restrict__ edbt,
    int E) {
    extern __shared__ float smem[];
    float* sE   = smem;               // TE*D : e after embedder
    float* sH   = sE + TE * D;        // TE*D : hidden buffer
    float* sW   = sH + TE * D;        // KC*D : weight staging
    float* sA   = sW + KC * D;        // TE*KC: gathered A staging
    int*   sIdx = reinterpret_cast<int*>(sA + TE * KC);   // [src x TE | dst x TE]
    float* sEf  = reinterpret_cast<float*>(sIdx + 2 * TE);// TE*4

    const int tid = threadIdx.x, wid = tid >> 5, tx = tid & 31;
    const int e0 = blockIdx.x * TE;

    if (tid < TE) {
        int e = min(e0 + tid, E - 1);
        sIdx[tid]      = eidx[e];       // src (mesh)
        sIdx[TE + tid] = eidx[E + e];   // dst (grid)
    }
    if (tid < TE * 4) {
        int e = min(e0 + (tid >> 2), E - 1);
        sEf[tid] = efeat[(size_t)e * 4 + (tid & 3)];
    }
    __syncthreads();

    float2 acc[4][8];

    // ---- phase 1: h = silu(ef @ embW0 + b0)  (K=4, weights from L1/L2) ----
    init_bias(acc, embb0, tx);
#pragma unroll
    for (int i = 0; i < 4; ++i) {
        int r = wid * 4 + i;
        float a0 = sEf[r * 4 + 0], a1 = sEf[r * 4 + 1];
        float a2 = sEf[r * 4 + 2], a3 = sEf[r * 4 + 3];
#pragma unroll
        for (int j = 0; j < 8; ++j) {
            int c = 64 * j + 2 * tx;
            float2 w0 = *reinterpret_cast<const float2*>(&embW0[0 * D + c]);
            float2 w1 = *reinterpret_cast<const float2*>(&embW0[1 * D + c]);
            float2 w2 = *reinterpret_cast<const float2*>(&embW0[2 * D + c]);
            float2 w3 = *reinterpret_cast<const float2*>(&embW0[3 * D + c]);
            acc[i][j].x += a0 * w0.x + a1 * w1.x + a2 * w2.x + a3 * w3.x;
            acc[i][j].y += a0 * w0.y + a1 * w1.y + a2 * w2.y + a3 * w3.y;
        }
    }
    silu_store(acc, sH, wid, tx);

    // ---- phase 2: e = LN(h @ embW1 + b1) -> sE ----
    init_bias(acc, embb1, tx);
    gemm_acc(acc, embW1, D, sW, tid, wid, tx,
             [](int) {},
             [&](int r, int k, int) { return sH[r * D + k]; });
    layernorm(acc, embg, embbt, tx);
#pragma unroll
    for (int i = 0; i < 4; ++i) {
        int r = wid * 4 + i;
#pragma unroll
        for (int j = 0; j < 8; ++j)
            *reinterpret_cast<float2*>(&sE[r * D + 64 * j + 2 * tx]) = acc[i][j];
    }

    // ---- phase 3: h = silu([e|mesh[src]|grid[dst]] @ edW0 + b0) ----
    init_bias(acc, edb0, tx);
    gemm_acc(acc, edW0, 3 * D, sW, tid, wid, tx,
             [&](int k0) {
                 if (k0 >= D) {
                     int row = tid >> 3, q = (tid & 7) * 2;
                     const float* src = (k0 < 2 * D)
                         ? mesh  + (size_t)sIdx[row]      * D + (k0 - D)     + q
                         : gridf + (size_t)sIdx[TE + row] * D + (k0 - 2 * D) + q;
                     *reinterpret_cast<float2*>(&sA[row * KC + q]) =
                         *reinterpret_cast<const float2*>(src);
                 }
             },
             [&](int r, int k, int kk) { return (k < D) ? sE[r * D + k] : sA[r * KC + kk]; });
    silu_store(acc, sH, wid, tx);

    // ---- phase 4: e_new = LN(h @ edW1 + b1) + e ; scatter-add to agg[dst] ----
    init_bias(acc, edb1, tx);
    gemm_acc(acc, edW1, D, sW, tid, wid, tx,
             [](int) {},
             [&](int r, int k, int) { return sH[r * D + k]; });
    layernorm(acc, edg, edbt, tx);
#pragma unroll
    for (int i = 0; i < 4; ++i) {
        int r = wid * 4 + i;
        if (e0 + r < E) {
            float* ap = g_agg + (size_t)sIdx[TE + r] * D;
#pragma unroll
            for (int j = 0; j < 8; ++j) {
                int c = 64 * j + 2 * tx;
                float2 e = *reinterpret_cast<const float2*>(&sE[r * D + c]);
                atomicAdd(ap + c,     acc[i][j].x + e.x);
                atomicAdd(ap + c + 1, acc[i][j].y + e.y);
            }
        }
    }
}

// Fused node MLP: out = LN(silu([grid|agg] @ nW0 + b0) @ nW1 + b1) + grid
__global__ void __launch_bounds__(NT, 1) node_kernel(
    const float* __restrict__ gridf,
    const float* __restrict__ nW0, const float* __restrict__ nb0,
    const float* __restrict__ nW1, const float* __restrict__ nb1,
    const float* __restrict__ ng,  const float* __restrict__ nbt,
    float* __restrict__ out, int NG) {
    extern __shared__ float smem[];
    float* sH = smem;            // TE*D
    float* sW = sH + TE * D;     // KC*D
    float* sA = sW + KC * D;     // TE*KC

    const int tid = threadIdx.x, wid = tid >> 5, tx = tid & 31;
    const int n0 = blockIdx.x * TE;

    float2 acc[4][8];
    init_bias(acc, nb0, tx);
    gemm_acc(acc, nW0, 2 * D, sW, tid, wid, tx,
             [&](int k0) {
                 int row = tid >> 3, q = (tid & 7) * 2;
                 int nr = min(n0 + row, NG - 1);
                 const float* src = (k0 < D)
                     ? gridf + (size_t)nr * D + k0       + q
                     : g_agg + (size_t)nr * D + (k0 - D) + q;
                 *reinterpret_cast<float2*>(&sA[row * KC + q]) =
                     *reinterpret_cast<const float2*>(src);
             },
             [&](int r, int, int kk) { return sA[r * KC + kk]; });
    silu_store(acc, sH, wid, tx);

    init_bias(acc, nb1, tx);
    gemm_acc(acc, nW1, D, sW, tid, wid, tx,
             [](int) {},
             [&](int r, int k, int) { return sH[r * D + k]; });
    layernorm(acc, ng, nbt, tx);

#pragma unroll
    for (int i = 0; i < 4; ++i) {
        int r = wid * 4 + i;
        if (n0 + r < NG) {
            size_t base = (size_t)(n0 + r) * D;
#pragma unroll
            for (int j = 0; j < 8; ++j) {
                int c = 64 * j + 2 * tx;
                float2 gr = *reinterpret_cast<const float2*>(&gridf[base + c]);
                float2 v;
                v.x = acc[i][j].x + gr.x;
                v.y = acc[i][j].y + gr.y;
                *reinterpret_cast<float2*>(&out[base + c]) = v;
            }
        }
    }
}

extern "C" void kernel_launch(void* const* d_in, const int* in_sizes, int n_in,
                              void* d_out, int out_size) {
    const float* gridf = (const float*)d_in[0];
    const float* mesh  = (const float*)d_in[1];
    const int*   eidx  = (const int*)  d_in[2];
    const float* efeat = (const float*)d_in[3];
    const float* embW0 = (const float*)d_in[4];
    const float* embb0 = (const float*)d_in[5];
    const float* embW1 = (const float*)d_in[6];
    const float* embb1 = (const float*)d_in[7];
    const float* embg  = (const float*)d_in[8];
    const float* embbt = (const float*)d_in[9];
    const float* edW0  = (const float*)d_in[10];
    const float* edb0  = (const float*)d_in[11];
    const float* edW1  = (const float*)d_in[12];
    const float* edb1  = (const float*)d_in[13];
    const float* edg   = (const float*)d_in[14];
    const float* edbt  = (const float*)d_in[15];
    const float* ndW0  = (const float*)d_in[16];
    const float* ndb0  = (const float*)d_in[17];
    const float* ndW1  = (const float*)d_in[18];
    const float* ndb1  = (const float*)d_in[19];
    const float* ndg   = (const float*)d_in[20];
    const float* ndbt  = (const float*)d_in[21];
    float* out = (float*)d_out;

    const int NG = in_sizes[0] / D;
    const int E  = in_sizes[2] / 2;

    const int smemE = (2 * TE * D + KC * D + TE * KC) * 4 + 2 * TE * 4 + TE * 4 * 4;
    const int smemN = (TE * D + KC * D + TE * KC) * 4;
    cudaFuncSetAttribute(edge_kernel, cudaFuncAttributeMaxDynamicSharedMemorySize, smemE);
    cudaFuncSetAttribute(node_kernel, cudaFuncAttributeMaxDynamicSharedMemorySize, smemN);

    int n4 = NG * D / 4;
    zero_kernel<<<(n4 + NT - 1) / NT, NT>>>(n4);
    edge_kernel<<<(E + TE - 1) / TE, NT, smemE>>>(
        gridf, mesh, eidx, efeat,
        embW0, embb0, embW1, embb1, embg, embbt,
        edW0, edb0, edW1, edb1, edg, edbt, E);
    node_kernel<<<(NG + TE - 1) / TE, NT, smemN>>>(
        gridf, ndW0, ndb0, ndW1, ndb1, ndg, ndbt, out, NG);
}

// round 4
// speedup vs baseline: 3.0246x; 3.0246x over previous
#include <cuda_runtime.h>
#include <cstdint>

#define DIM 512
#define BM 128
#define BN 256
#define NTHREADS 256
#define ASTRIDE 36

// smem byte offsets
#define OFF_BIAS 0
#define OFF_IDX  1024
#define OFF_EF   2048
#define OFF_W0   4096
#define OFF_A    14336
#define OFF_B    51200
#define SMEM_TOTAL 116736

#define WT_EMB1 0
#define WT_ED0  262144
#define WT_ED1  1048576
#define WT_ND0  1310720
#define WT_ND1  1835008

__device__ float g_wt[2097152];
__device__ float g_e [(size_t)196608 * DIM];
__device__ float g_h [(size_t)196608 * DIM];
__device__ float g_z [(size_t)196608 * DIM];
__device__ float g_agg[(size_t)65536 * DIM];

__device__ __forceinline__ uint32_t smem_u32(const void* p) {
    uint32_t a;
    asm("{ .reg .u64 t; cvta.to.shared.u64 t, %1; cvt.u32.u64 %0, t; }" : "=r"(a) : "l"(p));
    return a;
}
__device__ __forceinline__ float rtf(float x) {
    uint32_t r; asm("cvt.rna.tf32.f32 %0, %1;" : "=r"(r) : "f"(x));
    return __uint_as_float(r);
}
__device__ __forceinline__ void cp16(uint32_t dst, const void* src) {
    asm volatile("cp.async.cg.shared.global [%0], [%1], 16;" :: "r"(dst), "l"(src));
}
__device__ __forceinline__ float silu(float x) { return __fdividef(x, 1.0f + __expf(-x)); }

__device__ __forceinline__ void mma8(float* d, const uint32_t* a, const uint32_t* b) {
    asm volatile(
        "mma.sync.aligned.m16n8k8.row.col.f32.tf32.tf32.f32 "
        "{%0,%1,%2,%3},{%4,%5,%6,%7},{%8,%9},{%0,%1,%2,%3};"
        : "+f"(d[0]), "+f"(d[1]), "+f"(d[2]), "+f"(d[3])
        : "r"(a[0]), "r"(a[1]), "r"(a[2]), "r"(a[3]), "r"(b[0]), "r"(b[1]));
}

// ---- weight prep: W[k][n] row-major -> fragment-ordered g_wt, tf32-rounded ----
__global__ void prep_w(const float* __restrict__ W, int KTOT, int woff) {
    int gid = blockIdx.x * 256 + threadIdx.x;
    int chunk = gid >> 13;
    int rem   = gid & 8191;
    int k8    = rem >> 11;
    int ntl   = (rem >> 6) & 31;
    int lane  = (rem >> 1) & 31;
    int s     = rem & 1;
    int cpc   = KTOT / 32;
    int colhalf = chunk / cpc;
    int c       = chunk % cpc;
    int k = c * 32 + k8 * 8 + (lane & 3) + s * 4;
    int n = colhalf * 256 + ntl * 8 + (lane >> 2);
    g_wt[woff + gid] = rtf(W[(size_t)k * DIM + n]);
}

__global__ void zero_kernel(int n4) {
    int i = blockIdx.x * blockDim.x + threadIdx.x;
    if (i < n4) *reinterpret_cast<float4*>(&g_agg[(size_t)i * 4]) = make_float4(0.f, 0.f, 0.f, 0.f);
}

struct GP {
    const float *a0, *a1;
    const int   *eidx;
    const float *ef, *W0s, *b0s, *bias;
    int woff, E;
};

// ASRC: 0 = compute silu(ef@W0+b0); 1 = [g_e | mesh[src] | grid[dst]];
//       2 = g_h; 3 = [grid | g_agg]
// SILU: epilogue silu(acc+bias) -> g_h; else raw acc -> g_z
template <int KTOT, int ASRC, bool SILU>
__global__ void __launch_bounds__(NTHREADS, 1) gemm_k(GP p) {
    extern __shared__ char smem[];
    float* smf  = (float*)smem;
    float* sA   = (float*)(smem + OFF_A);
    float* sB   = (float*)(smem + OFF_B);
    int*   sidx = (int*)(smem + OFF_IDX);
    const uint32_t sBu = smem_u32(sB);

    const int tid = threadIdx.x;
    const int wid = tid >> 5, lane = tid & 31;
    const int r0 = blockIdx.x * BM;
    const int colhalf = blockIdx.y;
    const int wm = (wid >> 2) * 64;
    const int wnq = wid & 3;

    if (SILU)
        for (int i = tid; i < 256; i += NTHREADS)
            smf[OFF_BIAS / 4 + i] = p.bias[colhalf * 256 + i];
    if (ASRC == 0) {
        for (int i = tid; i < 2048; i += NTHREADS) smf[OFF_W0 / 4 + i] = p.W0s[i];
        for (int i = tid; i < 512; i += NTHREADS)  smf[OFF_W0 / 4 + 2048 + i] = p.b0s[i];
        for (int i = tid; i < 512; i += NTHREADS)
            smf[OFF_EF / 4 + i] = p.ef[(size_t)(r0 + (i >> 2)) * 4 + (i & 3)];
    }
    if (ASRC == 1 && tid < 256)
        sidx[tid] = (tid < 128) ? p.eidx[r0 + tid] : p.eidx[p.E + r0 + tid - 128];
    __syncthreads();

    auto loadA = [&](int c, int buf) {
        float* dst = sA + buf * (BM * ASTRIDE);
        if (ASRC == 0) {
            const float* w0 = smf + OFF_W0 / 4;
#pragma unroll
            for (int i = 0; i < 4; ++i) {
                int idx = tid + i * 256;
                int r = idx >> 3, q = idx & 7;
                const float* efr = smf + OFF_EF / 4 + r * 4;
                float e0 = efr[0], e1 = efr[1], e2 = efr[2], e3 = efr[3];
                float vv[4];
#pragma unroll
                for (int j = 0; j < 4; ++j) {
                    int col = c * 32 + q * 4 + j;
                    float v = w0[2048 + col] + e0 * w0[col] + e1 * w0[512 + col]
                            + e2 * w0[1024 + col] + e3 * w0[1536 + col];
                    vv[j] = rtf(silu(v));
                }
                float* d = dst + r * ASTRIDE + q * 4;
                *(float2*)d       = make_float2(vv[0], vv[1]);
                *(float2*)(d + 2) = make_float2(vv[2], vv[3]);
            }
        } else {
            int k0 = c * 32;
#pragma unroll
            for (int i = 0; i < 4; ++i) {
                int idx = tid + i * 256;
                int r = idx >> 3, q = idx & 7;
                const float* ptr;
                if (ASRC == 1) {
                    if (k0 < 512)       ptr = g_e  + (size_t)(r0 + r) * DIM + k0 + q * 4;
                    else if (k0 < 1024) ptr = p.a0 + (size_t)sidx[r] * DIM + (k0 - 512) + q * 4;
                    else                ptr = p.a1 + (size_t)sidx[128 + r] * DIM + (k0 - 1024) + q * 4;
                } else if (ASRC == 3) {
                    ptr = (k0 < 512) ? p.a0  + (size_t)(r0 + r) * DIM + k0 + q * 4
                                     : g_agg + (size_t)(r0 + r) * DIM + (k0 - 512) + q * 4;
                } else {
                    ptr = g_h + (size_t)(r0 + r) * DIM + k0 + q * 4;
                }
                float4 v = *(const float4*)ptr;
                float* d = dst + r * ASTRIDE + q * 4;
                *(float2*)d       = make_float2(rtf(v.x), rtf(v.y));
                *(float2*)(d + 2) = make_float2(rtf(v.z), rtf(v.w));
            }
        }
    };
    auto loadB = [&](int c, int buf) {
        const float* src = g_wt + p.woff + (size_t)(colhalf * (KTOT / 32) + c) * 8192;
        uint32_t dst = sBu + buf * 32768;
#pragma unroll
        for (int i = 0; i < 8; ++i) {
            int idx = tid + i * 256;
            cp16(dst + idx * 16, src + idx * 4);
        }
    };

    constexpr int C = KTOT / 32;
    float acc[4][8][4];
#pragma unroll
    for (int m = 0; m < 4; ++m)
#pragma unroll
        for (int n = 0; n < 8; ++n)
#pragma unroll
            for (int t = 0; t < 4; ++t) acc[m][n][t] = 0.f;

    loadB(0, 0);
    loadA(0, 0);
    asm volatile("cp.async.commit_group;" ::: "memory");

    for (int c = 0; c < C; ++c) {
        int buf = c & 1;
        if (c + 1 < C) {
            loadB(c + 1, buf ^ 1);
            loadA(c + 1, buf ^ 1);
            asm volatile("cp.async.commit_group;" ::: "memory");
            asm volatile("cp.async.wait_group 1;" ::: "memory");
        } else {
            asm volatile("cp.async.wait_group 0;" ::: "memory");
        }
        __syncthreads();
        const float* A = sA + buf * (BM * ASTRIDE);
        const float* B = sB + buf * 8192;
#pragma unroll
        for (int k8 = 0; k8 < 4; ++k8) {
            uint32_t a[4][4];
#pragma unroll
            for (int mt = 0; mt < 4; ++mt) {
                const float* ap = A + (wm + mt * 16 + (lane >> 2)) * ASTRIDE + k8 * 8 + (lane & 3);
                a[mt][0] = __float_as_uint(ap[0]);
                a[mt][1] = __float_as_uint(ap[8 * ASTRIDE]);
                a[mt][2] = __float_as_uint(ap[4]);
                a[mt][3] = __float_as_uint(ap[8 * ASTRIDE + 4]);
            }
            uint32_t b[8][2];
#pragma unroll
            for (int nt = 0; nt < 8; ++nt) {
                float2 bv = *(const float2*)(B + k8 * 2048 + (wnq * 8 + nt) * 64 + lane * 2);
                b[nt][0] = __float_as_uint(bv.x);
                b[nt][1] = __float_as_uint(bv.y);
            }
#pragma unroll
            for (int mt = 0; mt < 4; ++mt)
#pragma unroll
                for (int nt = 0; nt < 8; ++nt)
                    mma8(acc[mt][nt], a[mt], b[nt]);
        }
        __syncthreads();
    }

    const int cbase = colhalf * 256 + wnq * 64;
#pragma unroll
    for (int mt = 0; mt < 4; ++mt) {
        int r_lo = r0 + wm + mt * 16 + (lane >> 2);
#pragma unroll
        for (int nt = 0; nt < 8; ++nt) {
            int cl = wnq * 64 + nt * 8 + (lane & 3) * 2;
            int col = colhalf * 256 + cl;
            if (SILU) {
                float b0v = smf[OFF_BIAS / 4 + cl];
                float b1v = smf[OFF_BIAS / 4 + cl + 1];
                *(float2*)(g_h + (size_t)r_lo * DIM + col) =
                    make_float2(silu(acc[mt][nt][0] + b0v), silu(acc[mt][nt][1] + b1v));
                *(float2*)(g_h + (size_t)(r_lo + 8) * DIM + col) =
                    make_float2(silu(acc[mt][nt][2] + b0v), silu(acc[mt][nt][3] + b1v));
            } else {
                *(float2*)(g_z + (size_t)r_lo * DIM + col) =
                    make_float2(acc[mt][nt][0], acc[mt][nt][1]);
                *(float2*)(g_z + (size_t)(r_lo + 8) * DIM + col) =
                    make_float2(acc[mt][nt][2], acc[mt][nt][3]);
            }
        }
    }
    (void)cbase;
}

// ---- LN kernels: z -> bias+LN (+residual / scatter) ----
// M=0: -> g_e ; M=2: + g_e, atomicAdd into g_agg[dst] ; M=4: + res -> outp
template <int M>
__global__ void __launch_bounds__(256) ln_k(
    const float* __restrict__ bias, const float* __restrict__ gam,
    const float* __restrict__ bet,  const float* __restrict__ res,
    const int* __restrict__ eidx,   float* __restrict__ outp, int E) {
    int row = blockIdx.x * 8 + (threadIdx.x >> 5);
    int lane = threadIdx.x & 31;
    const float* z = g_z + (size_t)row * DIM;
    float v[16];
    float s = 0.f, ss = 0.f;
#pragma unroll
    for (int j = 0; j < 4; ++j) {
        int col = j * 128 + lane * 4;
        float4 zz = *(const float4*)(z + col);
        float4 bb = *(const float4*)(bias + col);
        v[j * 4 + 0] = zz.x + bb.x; v[j * 4 + 1] = zz.y + bb.y;
        v[j * 4 + 2] = zz.z + bb.z; v[j * 4 + 3] = zz.w + bb.w;
#pragma unroll
        for (int t = 0; t < 4; ++t) { s += v[j * 4 + t]; ss += v[j * 4 + t] * v[j * 4 + t]; }
    }
#pragma unroll
    for (int o = 16; o; o >>= 1) {
        s  += __shfl_xor_sync(0xffffffffu, s, o);
        ss += __shfl_xor_sync(0xffffffffu, ss, o);
    }
    float m = s * (1.0f / DIM);
    float rstd = rsqrtf(ss * (1.0f / DIM) - m * m + 1e-5f);
#pragma unroll
    for (int j = 0; j < 4; ++j) {
        int col = j * 128 + lane * 4;
        float4 gg = *(const float4*)(gam + col);
        float4 bt = *(const float4*)(bet + col);
        float o0 = (v[j * 4 + 0] - m) * rstd * gg.x + bt.x;
        float o1 = (v[j * 4 + 1] - m) * rstd * gg.y + bt.y;
        float o2 = (v[j * 4 + 2] - m) * rstd * gg.z + bt.z;
        float o3 = (v[j * 4 + 3] - m) * rstd * gg.w + bt.w;
        if (M == 0) {
            *(float4*)(g_e + (size_t)row * DIM + col) = make_float4(o0, o1, o2, o3);
        } else if (M == 2) {
            float4 e = *(const float4*)(g_e + (size_t)row * DIM + col);
            float* ap = g_agg + (size_t)eidx[E + row] * DIM + col;
            atomicAdd(ap + 0, o0 + e.x); atomicAdd(ap + 1, o1 + e.y);
            atomicAdd(ap + 2, o2 + e.z); atomicAdd(ap + 3, o3 + e.w);
        } else {
            float4 rr = *(const float4*)(res + (size_t)row * DIM + col);
            *(float4*)(outp + (size_t)row * DIM + col) =
                make_float4(o0 + rr.x, o1 + rr.y, o2 + rr.z, o3 + rr.w);
        }
    }
}

extern "C" void kernel_launch(void* const* d_in, const int* in_sizes, int n_in,
                              void* d_out, int out_size) {
    const float* gridf = (const float*)d_in[0];
    const float* mesh  = (const float*)d_in[1];
    const int*   eidx  = (const int*)  d_in[2];
    const float* efeat = (const float*)d_in[3];
    const float* embW0 = (const float*)d_in[4];
    const float* embb0 = (const float*)d_in[5];
    const float* embW1 = (const float*)d_in[6];
    const float* embb1 = (const float*)d_in[7];
    const float* embg  = (const float*)d_in[8];
    const float* embbt = (const float*)d_in[9];
    const float* edW0  = (const float*)d_in[10];
    const float* edb0  = (const float*)d_in[11];
    const float* edW1  = (const float*)d_in[12];
    const float* edb1  = (const float*)d_in[13];
    const float* edg   = (const float*)d_in[14];
    const float* edbt  = (const float*)d_in[15];
    const float* ndW0  = (const float*)d_in[16];
    const float* ndb0  = (const float*)d_in[17];
    const float* ndW1  = (const float*)d_in[18];
    const float* ndb1  = (const float*)d_in[19];
    const float* ndg   = (const float*)d_in[20];
    const float* ndbt  = (const float*)d_in[21];

    const int NG = in_sizes[0] / DIM;
    const int E  = in_sizes[2] / 2;

    cudaFuncSetAttribute(gemm_k<512, 0, false>,  cudaFuncAttributeMaxDynamicSharedMemorySize, SMEM_TOTAL);
    cudaFuncSetAttribute(gemm_k<1536, 1, true>,  cudaFuncAttributeMaxDynamicSharedMemorySize, SMEM_TOTAL);
    cudaFuncSetAttribute(gemm_k<512, 2, false>,  cudaFuncAttributeMaxDynamicSharedMemorySize, SMEM_TOTAL);
    cudaFuncSetAttribute(gemm_k<1024, 3, true>,  cudaFuncAttributeMaxDynamicSharedMemorySize, SMEM_TOTAL);

    prep_w<<<512 * 512 / 256, 256>>>(embW1, 512,  WT_EMB1);
    prep_w<<<1536 * 512 / 256, 256>>>(edW0, 1536, WT_ED0);
    prep_w<<<512 * 512 / 256, 256>>>(edW1, 512,  WT_ED1);
    prep_w<<<1024 * 512 / 256, 256>>>(ndW0, 1024, WT_ND0);
    prep_w<<<512 * 512 / 256, 256>>>(ndW1, 512,  WT_ND1);

    int n4 = NG * DIM / 4;
    zero_kernel<<<(n4 + 255) / 256, 256>>>(n4);

    dim3 gE(E / BM, 2), gN(NG / BM, 2);

    GP p0{}; p0.ef = efeat; p0.W0s = embW0; p0.b0s = embb0;
    p0.woff = WT_EMB1; p0.E = E;
    gemm_k<512, 0, false><<<gE, NTHREADS, SMEM_TOTAL>>>(p0);
    ln_k<0><<<E / 8, 256>>>(embb1, embg, embbt, nullptr, nullptr, nullptr, E);

    GP p1{}; p1.a0 = mesh; p1.a1 = gridf; p1.eidx = eidx;
    p1.bias = edb0; p1.woff = WT_ED0; p1.E = E;
    gemm_k<1536, 1, true><<<gE, NTHREADS, SMEM_TOTAL>>>(p1);

    GP p2{}; p2.woff = WT_ED1; p2.E = E;
    gemm_k<512, 2, false><<<gE, NTHREADS, SMEM_TOTAL>>>(p2);
    ln_k<2><<<E / 8, 256>>>(edb1, edg, edbt, nullptr, eidx, nullptr, E);

    GP p3{}; p3.a0 = gridf; p3.bias = ndb0; p3.woff = WT_ND0; p3.E = E;
    gemm_k<1024, 3, true><<<gN, NTHREADS, SMEM_TOTAL>>>(p3);

    GP p4{}; p4.woff = WT_ND1; p4.E = E;
    gemm_k<512, 2, false><<<gN, NTHREADS, SMEM_TOTAL>>>(p4);
    ln_k<4><<<NG / 8, 256>>>(ndb1, ndg, ndbt, gridf, nullptr, (float*)d_out, E);
}

// round 5
// speedup vs baseline: 6.8458x; 2.2634x over previous
#include <cuda_runtime.h>
#include <cuda_fp16.h>
#include <cstdint>

#define DIM 512
#define BM 128
#define NTHREADS 256

#define APITCH 80
#define ABUF 10240
#define BBUF 16384
#define OFF_BIAS 0
#define OFF_IDX  1024
#define OFF_EF   2048
#define OFF_W0   4096
#define OFF_A    14336
#define OFF_B    34816
#define SMEM_TOTAL 67584

#define WT_EMB1 0
#define WT_ED0  262144
#define WT_ED1  1048576
#define WT_ND0  1310720
#define WT_ND1  1835008

__device__ __half g_wt[2097152];
__device__ __half g_e [(size_t)196608 * DIM];
__device__ __half g_h [(size_t)196608 * DIM];
__device__ float  g_z [(size_t)196608 * DIM];
__device__ float  g_agg[(size_t)65536 * DIM];

__device__ __forceinline__ uint32_t smem_u32(const void* p) {
    uint32_t a;
    asm("{ .reg .u64 t; cvta.to.shared.u64 t, %1; cvt.u32.u64 %0, t; }" : "=r"(a) : "l"(p));
    return a;
}
__device__ __forceinline__ void cp16(uint32_t dst, const void* src) {
    asm volatile("cp.async.cg.shared.global [%0], [%1], 16;" :: "r"(dst), "l"(src));
}
__device__ __forceinline__ float silu(float x) { return __fdividef(x, 1.0f + __expf(-x)); }

__device__ __forceinline__ void mma16816(float* d, const uint32_t* a, const uint32_t* b) {
    asm volatile(
        "mma.sync.aligned.m16n8k16.row.col.f32.f16.f16.f32 "
        "{%0,%1,%2,%3},{%4,%5,%6,%7},{%8,%9},{%0,%1,%2,%3};"
        : "+f"(d[0]), "+f"(d[1]), "+f"(d[2]), "+f"(d[3])
        : "r"(a[0]), "r"(a[1]), "r"(a[2]), "r"(a[3]), "r"(b[0]), "r"(b[1]));
}
__device__ __forceinline__ void ldmA(uint32_t* r, uint32_t addr) {
    asm volatile("ldmatrix.sync.aligned.m8n8.x4.shared.b16 {%0,%1,%2,%3}, [%4];"
                 : "=r"(r[0]), "=r"(r[1]), "=r"(r[2]), "=r"(r[3]) : "r"(addr));
}

// W[k][n] row-major fp32 -> fp16 fragment-ordered g_wt
__global__ void prep_w(const float* __restrict__ W, int KTOT, int woff) {
    int gid = blockIdx.x * 256 + threadIdx.x;
    int r    = gid & 1;
    int lane = (gid >> 1) & 31;
    int nt   = (gid >> 6) & 31;
    int u    = (gid >> 11) & 1;
    int block = gid >> 12;
    int cpc = KTOT / 32;
    int colhalf = block / cpc;
    int c = block % cpc;
    int k = c * 32 + u * 16 + (lane & 3) * 2 + r * 8;
    int n = colhalf * 256 + nt * 8 + (lane >> 2);
    ((__half2*)g_wt)[woff / 2 + gid] =
        __floats2half2_rn(W[(size_t)k * DIM + n], W[(size_t)(k + 1) * DIM + n]);
}

__global__ void zero_kernel(int n4) {
    int i = blockIdx.x * blockDim.x + threadIdx.x;
    if (i < n4) *reinterpret_cast<float4*>(&g_agg[(size_t)i * 4]) = make_float4(0.f, 0.f, 0.f, 0.f);
}

struct GP {
    const float *a0, *a1;
    const int   *eidx;
    const float *ef, *W0s, *b0s, *bias;
    int woff, E;
};

// STYLE 0: A = silu(ef@W0+b0) computed in-kernel
// STYLE 1: A = [g_e fp16 | mesh[src] fp32 | grid[dst] fp32]
// STYLE 2: A = g_h fp16
// STYLE 3: A = [grid fp32 | g_agg fp32]
template <int KTOT, int STYLE, bool SILU>
__global__ void __launch_bounds__(NTHREADS, 1) gemm_k(GP p) {
    extern __shared__ char smem[];
    float* smf  = (float*)smem;
    int*   sidx = (int*)(smem + OFF_IDX);
    const uint32_t sAu = smem_u32(smem + OFF_A);
    const uint32_t sBu = smem_u32(smem + OFF_B);

    const int tid = threadIdx.x, wid = tid >> 5, lane = tid & 31;
    const int r0 = blockIdx.x * BM;
    const int colhalf = blockIdx.y;
    const int wm = (wid >> 2) * 64, wnq = wid & 3;
    constexpr int C = KTOT / 32;

    if (SILU)
        for (int i = tid; i < 256; i += NTHREADS)
            smf[OFF_BIAS / 4 + i] = p.bias[colhalf * 256 + i];
    if (STYLE == 0) {
        for (int i = tid; i < 2048; i += NTHREADS) smf[OFF_W0 / 4 + i] = p.W0s[i];
        for (int i = tid; i < 512; i += NTHREADS)  smf[OFF_W0 / 4 + 2048 + i] = p.b0s[i];
        for (int i = tid; i < 512; i += NTHREADS)
            smf[OFF_EF / 4 + i] = p.ef[(size_t)(r0 + (i >> 2)) * 4 + (i & 3)];
    }
    if (STYLE == 1 && tid < 256)
        sidx[tid] = (tid < 128) ? p.eidx[r0 + tid] : p.eidx[p.E + r0 + tid - 128];
    __syncthreads();

    float4 v[4];

    auto prefetchA = [&](int c) {
        if (STYLE == 0 || STYLE == 2) return;
        int k0 = c * 32;
        if (STYLE == 1 && k0 < 512) return;
#pragma unroll
        for (int i = 0; i < 4; ++i) {
            int idx = tid + i * 256;
            int r = idx >> 3, q = idx & 7;
            const float* ptr;
            if (STYLE == 1) {
                ptr = (k0 < 1024) ? p.a0 + (size_t)sidx[r] * DIM + (k0 - 512) + q * 4
                                  : p.a1 + (size_t)sidx[128 + r] * DIM + (k0 - 1024) + q * 4;
            } else {
                ptr = (k0 < 512) ? p.a0  + (size_t)(r0 + r) * DIM + k0 + q * 4
                                 : g_agg + (size_t)(r0 + r) * DIM + (k0 - 512) + q * 4;
            }
            v[i] = *(const float4*)ptr;
        }
    };
    auto stageA = [&](int c, int buf) {
        uint32_t ab = sAu + buf * ABUF;
        int k0 = c * 32;
        if (STYLE == 0) {
            const float* w0 = smf + OFF_W0 / 4;
#pragma unroll
            for (int i = 0; i < 4; ++i) {
                int idx = tid + i * 256;
                int r = idx >> 3, q = idx & 7;
                const float* efr = smf + OFF_EF / 4 + r * 4;
                float e0 = efr[0], e1 = efr[1], e2 = efr[2], e3 = efr[3];
                float o[4];
#pragma unroll
                for (int j = 0; j < 4; ++j) {
                    int col = k0 + q * 4 + j;
                    o[j] = silu(w0[2048 + col] + e0 * w0[col] + e1 * w0[512 + col]
                                + e2 * w0[1024 + col] + e3 * w0[1536 + col]);
                }
                __half2 h0 = __floats2half2_rn(o[0], o[1]);
                __half2 h1 = __floats2half2_rn(o[2], o[3]);
                asm volatile("st.shared.v2.b32 [%0], {%1,%2};"
                             :: "r"(ab + r * APITCH + q * 8),
                                "r"(*(uint32_t*)&h0), "r"(*(uint32_t*)&h1));
            }
        } else if (STYLE == 2 || (STYLE == 1 && k0 < 512)) {
            const __half* src = (STYLE == 2) ? g_h : g_e;
#pragma unroll
            for (int i = 0; i < 2; ++i) {
                int idx = tid + i * 256;
                int r = idx >> 2, q = idx & 3;
                cp16(ab + r * APITCH + q * 16,
                     src + (size_t)(r0 + r) * DIM + k0 + q * 8);
            }
        } else {
#pragma unroll
            for (int i = 0; i < 4; ++i) {
                int idx = tid + i * 256;
                int r = idx >> 3, q = idx & 7;
                __half2 h0 = __floats2half2_rn(v[i].x, v[i].y);
                __half2 h1 = __floats2half2_rn(v[i].z, v[i].w);
                asm volatile("st.shared.v2.b32 [%0], {%1,%2};"
                             :: "r"(ab + r * APITCH + q * 8),
                                "r"(*(uint32_t*)&h0), "r"(*(uint32_t*)&h1));
            }
        }
    };
    auto stageB = [&](int c, int buf) {
        const __half* src = g_wt + p.woff + (size_t)(colhalf * C + c) * 8192;
        uint32_t dst = sBu + buf * BBUF;
#pragma unroll
        for (int i = 0; i < 4; ++i) {
            int idx = tid + i * 256;
            cp16(dst + idx * 16, src + idx * 8);
        }
    };

    float acc[4][8][4];
#pragma unroll
    for (int m = 0; m < 4; ++m)
#pragma unroll
        for (int n = 0; n < 8; ++n)
#pragma unroll
            for (int t = 0; t < 4; ++t) acc[m][n][t] = 0.f;

    prefetchA(0);
    stageA(0, 0);
    stageB(0, 0);
    asm volatile("cp.async.commit_group;" ::: "memory");
    prefetchA(1);

    for (int c = 0; c < C; ++c) {
        int buf = c & 1;
        if (c + 1 < C) {
            stageA(c + 1, buf ^ 1);
            stageB(c + 1, buf ^ 1);
            asm volatile("cp.async.commit_group;" ::: "memory");
            if (c + 2 < C) prefetchA(c + 2);
            asm volatile("cp.async.wait_group 1;" ::: "memory");
        } else {
            asm volatile("cp.async.wait_group 0;" ::: "memory");
        }
        __syncthreads();
        uint32_t abase = sAu + buf * ABUF;
        uint32_t bbase = sBu + buf * BBUF;
        int sel = lane >> 3;
        uint32_t arowoff = (wm + (sel & 1) * 8 + (lane & 7)) * APITCH + (sel >> 1) * 16;
#pragma unroll
        for (int u = 0; u < 2; ++u) {
            uint32_t a[4][4];
#pragma unroll
            for (int mt = 0; mt < 4; ++mt)
                ldmA(a[mt], abase + arowoff + mt * (16 * APITCH) + u * 32);
            uint32_t b[8][2];
#pragma unroll
            for (int nt = 0; nt < 8; ++nt) {
                asm volatile("ld.shared.v2.b32 {%0,%1}, [%2];"
                             : "=r"(b[nt][0]), "=r"(b[nt][1])
                             : "r"(bbase + (((u * 32 + wnq * 8 + nt) * 32 + lane) * 8)));
            }
#pragma unroll
            for (int mt = 0; mt < 4; ++mt)
#pragma unroll
                for (int nt = 0; nt < 8; ++nt)
                    mma16816(acc[mt][nt], a[mt], b[nt]);
        }
        __syncthreads();
    }

#pragma unroll
    for (int mt = 0; mt < 4; ++mt) {
        int r_lo = r0 + wm + mt * 16 + (lane >> 2);
#pragma unroll
        for (int nt = 0; nt < 8; ++nt) {
            int cl = wnq * 64 + nt * 8 + (lane & 3) * 2;
            int col = colhalf * 256 + cl;
            if (SILU) {
                float b0v = smf[OFF_BIAS / 4 + cl];
                float b1v = smf[OFF_BIAS / 4 + cl + 1];
                *(__half2*)(g_h + (size_t)r_lo * DIM + col) =
                    __floats2half2_rn(silu(acc[mt][nt][0] + b0v), silu(acc[mt][nt][1] + b1v));
                *(__half2*)(g_h + (size_t)(r_lo + 8) * DIM + col) =
                    __floats2half2_rn(silu(acc[mt][nt][2] + b0v), silu(acc[mt][nt][3] + b1v));
            } else {
                *(float2*)(g_z + (size_t)r_lo * DIM + col) =
                    make_float2(acc[mt][nt][0], acc[mt][nt][1]);
                *(float2*)(g_z + (size_t)(r_lo + 8) * DIM + col) =
                    make_float2(acc[mt][nt][2], acc[mt][nt][3]);
            }
        }
    }
}

// M=0: -> g_e (fp16) ; M=2: + g_e, atomicAdd g_agg[dst] ; M=4: + res -> outp
template <int M>
__global__ void __launch_bounds__(256) ln_k(
    const float* __restrict__ bias, const float* __restrict__ gam,
    const float* __restrict__ bet,  const float* __restrict__ res,
    const int* __restrict__ eidx,   float* __restrict__ outp, int E) {
    int row = blockIdx.x * 8 + (threadIdx.x >> 5);
    int lane = threadIdx.x & 31;
    const float* z = g_z + (size_t)row * DIM;
    float vv[16];
    float s = 0.f, ss = 0.f;
#pragma unroll
    for (int j = 0; j < 4; ++j) {
        int col = j * 128 + lane * 4;
        float4 zz = *(const float4*)(z + col);
        float4 bb = *(const float4*)(bias + col);
        vv[j * 4 + 0] = zz.x + bb.x; vv[j * 4 + 1] = zz.y + bb.y;
        vv[j * 4 + 2] = zz.z + bb.z; vv[j * 4 + 3] = zz.w + bb.w;
#pragma unroll
        for (int t = 0; t < 4; ++t) { s += vv[j * 4 + t]; ss += vv[j * 4 + t] * vv[j * 4 + t]; }
    }
#pragma unroll
    for (int o = 16; o; o >>= 1) {
        s  += __shfl_xor_sync(0xffffffffu, s, o);
        ss += __shfl_xor_sync(0xffffffffu, ss, o);
    }
    float m = s * (1.0f / DIM);
    float rstd = rsqrtf(ss * (1.0f / DIM) - m * m + 1e-5f);
#pragma unroll
    for (int j = 0; j < 4; ++j) {
        int col = j * 128 + lane * 4;
        float4 gg = *(const float4*)(gam + col);
        float4 bt = *(const float4*)(bet + col);
        float o0 = (vv[j * 4 + 0] - m) * rstd * gg.x + bt.x;
        float o1 = (vv[j * 4 + 1] - m) * rstd * gg.y + bt.y;
        float o2 = (vv[j * 4 + 2] - m) * rstd * gg.z + bt.z;
        float o3 = (vv[j * 4 + 3] - m) * rstd * gg.w + bt.w;
        if (M == 0) {
            __half2* ep = (__half2*)(g_e + (size_t)row * DIM + col);
            ep[0] = __floats2half2_rn(o0, o1);
            ep[1] = __floats2half2_rn(o2, o3);
        } else if (M == 2) {
            const __half2* ep = (const __half2*)(g_e + (size_t)row * DIM + col);
            float2 e01 = __half22float2(ep[0]);
            float2 e23 = __half22float2(ep[1]);
            float* ap = g_agg + (size_t)eidx[E + row] * DIM + col;
            atomicAdd(ap + 0, o0 + e01.x); atomicAdd(ap + 1, o1 + e01.y);
            atomicAdd(ap + 2, o2 + e23.x); atomicAdd(ap + 3, o3 + e23.y);
        } else {
            float4 rr = *(const float4*)(res + (size_t)row * DIM + col);
            *(float4*)(outp + (size_t)row * DIM + col) =
                make_float4(o0 + rr.x, o1 + rr.y, o2 + rr.z, o3 + rr.w);
        }
    }
}

extern "C" void kernel_launch(void* const* d_in, const int* in_sizes, int n_in,
                              void* d_out, int out_size) {
    const float* gridf = (const float*)d_in[0];
    const float* mesh  = (const float*)d_in[1];
    const int*   eidx  = (const int*)  d_in[2];
    const float* efeat = (const float*)d_in[3];
    const float* embW0 = (const float*)d_in[4];
    const float* embb0 = (const float*)d_in[5];
    const float* embW1 = (const float*)d_in[6];
    const float* embb1 = (const float*)d_in[7];
    const float* embg  = (const float*)d_in[8];
    const float* embbt = (const float*)d_in[9];
    const float* edW0  = (const float*)d_in[10];
    const float* edb0  = (const float*)d_in[11];
    const float* edW1  = (const float*)d_in[12];
    const float* edb1  = (const float*)d_in[13];
    const float* edg   = (const float*)d_in[14];
    const float* edbt  = (const float*)d_in[15];
    const float* ndW0  = (const float*)d_in[16];
    const float* ndb0  = (const float*)d_in[17];
    const float* ndW1  = (const float*)d_in[18];
    const float* ndb1  = (const float*)d_in[19];
    const float* ndg   = (const float*)d_in[20];
    const float* ndbt  = (const float*)d_in[21];

    const int NG = in_sizes[0] / DIM;
    const int E  = in_sizes[2] / 2;

    cudaFuncSetAttribute(gemm_k<512, 0, false>,  cudaFuncAttributeMaxDynamicSharedMemorySize, SMEM_TOTAL);
    cudaFuncSetAttribute(gemm_k<1536, 1, true>,  cudaFuncAttributeMaxDynamicSharedMemorySize, SMEM_TOTAL);
    cudaFuncSetAttribute(gemm_k<512, 2, false>,  cudaFuncAttributeMaxDynamicSharedMemorySize, SMEM_TOTAL);
    cudaFuncSetAttribute(gemm_k<1024, 3, true>,  cudaFuncAttributeMaxDynamicSharedMemorySize, SMEM_TOTAL);

    prep_w<<<512,  256>>>(embW1, 512,  WT_EMB1);
    prep_w<<<1536, 256>>>(edW0,  1536, WT_ED0);
    prep_w<<<512,  256>>>(edW1,  512,  WT_ED1);
    prep_w<<<1024, 256>>>(ndW0,  1024, WT_ND0);
    prep_w<<<512,  256>>>(ndW1,  512,  WT_ND1);

    int n4 = NG * DIM / 4;
    zero_kernel<<<(n4 + 255) / 256, 256>>>(n4);

    dim3 gE(E / BM, 2), gN(NG / BM, 2);

    GP p0{}; p0.ef = efeat; p0.W0s = embW0; p0.b0s = embb0;
    p0.woff = WT_EMB1; p0.E = E;
    gemm_k<512, 0, false><<<gE, NTHREADS, SMEM_TOTAL>>>(p0);
    ln_k<0><<<E / 8, 256>>>(embb1, embg, embbt, nullptr, nullptr, nullptr, E);

    GP p1{}; p1.a0 = mesh; p1.a1 = gridf; p1.eidx = eidx;
    p1.bias = edb0; p1.woff = WT_ED0; p1.E = E;
    gemm_k<1536, 1, true><<<gE, NTHREADS, SMEM_TOTAL>>>(p1);

    GP p2{}; p2.woff = WT_ED1; p2.E = E;
    gemm_k<512, 2, false><<<gE, NTHREADS, SMEM_TOTAL>>>(p2);
    ln_k<2><<<E / 8, 256>>>(edb1, edg, edbt, nullptr, eidx, nullptr, E);

    GP p3{}; p3.a0 = gridf; p3.bias = ndb0; p3.woff = WT_ND0; p3.E = E;
    gemm_k<1024, 3, true><<<gN, NTHREADS, SMEM_TOTAL>>>(p3);

    GP p4{}; p4.woff = WT_ND1; p4.E = E;
    gemm_k<512, 2, false><<<gN, NTHREADS, SMEM_TOTAL>>>(p4);
    ln_k<4><<<NG / 8, 256>>>(ndb1, ndg, ndbt, gridf, nullptr, (float*)d_out, E);
}